// round 3
// baseline (speedup 1.0000x reference)
#include <cuda_runtime.h>
#include <math.h>

// QuantumPoolingLayer R3: two-kernel split.
//  K1: pool [64,64,64,512] fp32 -> per-sample 4 quadrant sums (scratch, 512 KB).
//      Fine granularity (2048 blocks of 256 KiB) to kill the wave tail.
//  K2: tanh + 4-qubit circuit per sample (32768 samples), writes <Z0>.

#define NQ 4

__device__ float g_quads[64 * 512 * 4];   // [sample n][quad], raw sums (static scratch)

struct c32 { float x, y; };
__device__ __forceinline__ c32 cadd(c32 a, c32 b){ return {a.x+b.x, a.y+b.y}; }
__device__ __forceinline__ c32 cmul(c32 a, c32 b){
    return { fmaf(a.x, b.x, -a.y*b.y), fmaf(a.x, b.y, a.y*b.x) };
}

// x[4] = tanh-normalized pooled values, w -> 24 floats [layer][qubit][phi,th,om].
__device__ __forceinline__ float simulate_sample(const float x[4], const float* __restrict__ w)
{
    c32 s[16];
#pragma unroll
    for (int k = 0; k < 16; k++) s[k] = {0.f, 0.f};
    s[0].x = 1.f;

    // Initial RY(x*pi); wire q <-> bit (3-q) => mask = 8>>q.
#pragma unroll
    for (int q = 0; q < NQ; q++) {
        float half = x[q] * 1.57079632679489662f;
        float sn, cs; __sincosf(half, &sn, &cs);
        const int m = 8 >> q;
#pragma unroll
        for (int k = 0; k < 16; k++) {
            if (!(k & m)) {
                c32 v0 = s[k], v1 = s[k | m];
                s[k]     = { cs*v0.x - sn*v1.x, cs*v0.y - sn*v1.y };
                s[k | m] = { sn*v0.x + cs*v1.x, sn*v0.y + cs*v1.y };
            }
        }
    }

#pragma unroll
    for (int layer = 0; layer < 2; layer++) {
#pragma unroll
        for (int q = 0; q < NQ; q++) {
            const float* g = w + (layer * 4 + q) * 3;
            float phi = g[0], th = g[1], om = g[2];
            float stt, ctt; __sincosf(0.5f * th, &stt, &ctt);
            float sa, ca;  __sincosf(0.5f * (phi + om), &sa, &ca);
            float sb, cb;  __sincosf(0.5f * (phi - om), &sb, &cb);
            c32 U00 = { ctt * ca, -ctt * sa };
            c32 U01 = { -stt * cb, -stt * sb };
            c32 U10 = { stt * cb, -stt * sb };
            c32 U11 = { ctt * ca,  ctt * sa };
            const int m = 8 >> q;
#pragma unroll
            for (int k = 0; k < 16; k++) {
                if (!(k & m)) {
                    c32 v0 = s[k], v1 = s[k | m];
                    s[k]     = cadd(cmul(U00, v0), cmul(U01, v1));
                    s[k | m] = cadd(cmul(U10, v0), cmul(U11, v1));
                }
            }
        }
        // CNOT(c,t) for all c<t in order: amplitude swaps.
#pragma unroll
        for (int c = 0; c < NQ; c++) {
#pragma unroll
            for (int t = c + 1; t < NQ; t++) {
                const int cm = 8 >> c, tm = 8 >> t;
#pragma unroll
                for (int k = 0; k < 16; k++) {
                    if ((k & cm) && !(k & tm)) {
                        c32 tmp = s[k]; s[k] = s[k | tm]; s[k | tm] = tmp;
                    }
                }
            }
        }
    }

    float p = 0.f;
#pragma unroll
    for (int k = 0; k < 16; k++) {
        float pr = fmaf(s[k].x, s[k].x, s[k].y * s[k].y);
        p += (k < 8) ? pr : -pr;
    }
    return p;
}

// K1: grid (mc=16, b=64, rh=2), 512 threads, 2 blocks/SM.
// Thread: lane=tid&7 (4 consecutive m), g=tid>>3: colhalf=g>>5, row=rh*32+(g&31).
// Sums 32 j values (its col half) of its float4 -> one quadrant partial.
__global__ void __launch_bounds__(512, 2)
pool_kernel(const float* __restrict__ in)
{
    const int mc = blockIdx.x;
    const int b  = blockIdx.y;
    const int rh = blockIdx.z;
    const int tid  = threadIdx.x;
    const int lane = tid & 7;
    const int g    = tid >> 3;           // 0..63
    const int ch   = g >> 5;             // col half
    const int row  = rh * 32 + (g & 31);

    const float* base = in
        + (((size_t)b * 64 + row) * 64 + ch * 32) * 512
        + mc * 32 + (lane << 2);

    float4 a = {0.f, 0.f, 0.f, 0.f};
#pragma unroll
    for (int j0 = 0; j0 < 32; j0 += 8) {
        float4 v[8];
#pragma unroll
        for (int k = 0; k < 8; k++)
            v[k] = __ldcs(reinterpret_cast<const float4*>(base + (size_t)(j0 + k) * 512));
#pragma unroll
        for (int k = 0; k < 8; k++) {
            a.x += v[k].x; a.y += v[k].y; a.z += v[k].z; a.w += v[k].w;
        }
    }

    __shared__ float4 part[2][32][8];    // [colhalf][row&31][lane], 8 KB
    part[ch][g & 31][lane] = a;
    __syncthreads();

    if (tid < 64) {
        const int c2 = tid >> 5;         // col half
        const int ml = tid & 31;         // m_local
        const float* pf = (const float*)part;
        float ssum = 0.f;
#pragma unroll
        for (int r = 0; r < 32; r++)
            ssum += pf[(c2 * 32 + r) * 32 + ml];
        const int mm = mc * 32 + ml;
        const int n  = b * 512 + mm;
        g_quads[n * 4 + rh * 2 + c2] = ssum;
    }
}

// K2: one thread per sample (32768).
__global__ void __launch_bounds__(256)
sim_kernel(const float* __restrict__ w, float* __restrict__ out)
{
    const int n = blockIdx.x * 256 + threadIdx.x;
    float4 qv = *reinterpret_cast<const float4*>(&g_quads[n * 4]);
    float x[4];
    x[0] = tanhf(qv.x * (1.0f / 1024.0f));
    x[1] = tanhf(qv.y * (1.0f / 1024.0f));
    x[2] = tanhf(qv.z * (1.0f / 1024.0f));
    x[3] = tanhf(qv.w * (1.0f / 1024.0f));
    const float* wp = w + (size_t)(n >> 6) * 24;
    out[n] = simulate_sample(x, wp);
}

extern "C" void kernel_launch(void* const* d_in, const int* in_sizes, int n_in,
                              void* d_out, int out_size)
{
    const float* in = (const float*)d_in[0];
    const float* w  = (const float*)d_in[1];
    if (n_in >= 2 && in_sizes[0] < in_sizes[1]) {   // defensive: identify by size
        in = (const float*)d_in[1];
        w  = (const float*)d_in[0];
    }
    dim3 grid1(16, 64, 2);
    pool_kernel<<<grid1, 512>>>(in);
    sim_kernel<<<128, 256>>>(w, (float*)d_out);
}

// round 4
// speedup vs baseline: 1.0105x; 1.0105x over previous
#include <cuda_runtime.h>
#include <math.h>

// QuantumPoolingLayer R4: single fine-grain pool kernel (2048 blocks, 256 KiB each)
// with last-pair-done sim tail. Sample (b,mm) needs blocks (mc,b,rh=0/1); the
// second finisher of each pair simulates that chunk's 32 samples in its tail,
// overlapped with other blocks' streaming. Self-resetting counters (graph-safe).

#define NQ 4

__device__ float g_quads[64 * 512 * 4];   // [sample n][quad] raw sums
__device__ int   g_cnt[16 * 64];          // per-(mc,b) pair counter, self-resetting

struct c32 { float x, y; };
__device__ __forceinline__ c32 cadd(c32 a, c32 b){ return {a.x+b.x, a.y+b.y}; }
__device__ __forceinline__ c32 cmul(c32 a, c32 b){
    return { fmaf(a.x, b.x, -a.y*b.y), fmaf(a.x, b.y, a.y*b.x) };
}

// x[4] = tanh-normalized pooled values, w -> 24 floats [layer][qubit][phi,th,om].
__device__ __forceinline__ float simulate_sample(const float x[4], const float* __restrict__ w)
{
    c32 s[16];
#pragma unroll
    for (int k = 0; k < 16; k++) s[k] = {0.f, 0.f};
    s[0].x = 1.f;

    // Initial RY(x*pi); wire q <-> bit (3-q) => mask = 8>>q.
#pragma unroll
    for (int q = 0; q < NQ; q++) {
        float half = x[q] * 1.57079632679489662f;
        float sn, cs; __sincosf(half, &sn, &cs);
        const int m = 8 >> q;
#pragma unroll
        for (int k = 0; k < 16; k++) {
            if (!(k & m)) {
                c32 v0 = s[k], v1 = s[k | m];
                s[k]     = { cs*v0.x - sn*v1.x, cs*v0.y - sn*v1.y };
                s[k | m] = { sn*v0.x + cs*v1.x, sn*v0.y + cs*v1.y };
            }
        }
    }

#pragma unroll
    for (int layer = 0; layer < 2; layer++) {
#pragma unroll
        for (int q = 0; q < NQ; q++) {
            const float* g = w + (layer * 4 + q) * 3;
            float phi = g[0], th = g[1], om = g[2];
            float stt, ctt; __sincosf(0.5f * th, &stt, &ctt);
            float sa, ca;  __sincosf(0.5f * (phi + om), &sa, &ca);
            float sb, cb;  __sincosf(0.5f * (phi - om), &sb, &cb);
            c32 U00 = { ctt * ca, -ctt * sa };
            c32 U01 = { -stt * cb, -stt * sb };
            c32 U10 = { stt * cb, -stt * sb };
            c32 U11 = { ctt * ca,  ctt * sa };
            const int m = 8 >> q;
#pragma unroll
            for (int k = 0; k < 16; k++) {
                if (!(k & m)) {
                    c32 v0 = s[k], v1 = s[k | m];
                    s[k]     = cadd(cmul(U00, v0), cadd(cmul(U01, v1), {0.f,0.f}));
                    s[k | m] = cadd(cmul(U10, v0), cmul(U11, v1));
                }
            }
        }
        // CNOT(c,t) for all c<t in order: amplitude swaps.
#pragma unroll
        for (int c = 0; c < NQ; c++) {
#pragma unroll
            for (int t = c + 1; t < NQ; t++) {
                const int cm = 8 >> c, tm = 8 >> t;
#pragma unroll
                for (int k = 0; k < 16; k++) {
                    if ((k & cm) && !(k & tm)) {
                        c32 tmp = s[k]; s[k] = s[k | tm]; s[k | tm] = tmp;
                    }
                }
            }
        }
    }

    float p = 0.f;
#pragma unroll
    for (int k = 0; k < 16; k++) {
        float pr = fmaf(s[k].x, s[k].x, s[k].y * s[k].y);
        p += (k < 8) ? pr : -pr;
    }
    return p;
}

// Grid (mc=16, b=64, rh=2), 512 threads, 2 blocks/SM.
// Thread: lane=tid&7 (4 consecutive m), g=tid>>3: colhalf=g>>5, row=rh*32+(g&31).
__global__ void __launch_bounds__(512, 2)
qpl_kernel(const float* __restrict__ in, const float* __restrict__ w, float* __restrict__ out)
{
    const int mc = blockIdx.x;
    const int b  = blockIdx.y;
    const int rh = blockIdx.z;
    const int tid  = threadIdx.x;
    const int lane = tid & 7;
    const int g    = tid >> 3;           // 0..63
    const int ch   = g >> 5;             // col half
    const int row  = rh * 32 + (g & 31);

    const float* base = in
        + (((size_t)b * 64 + row) * 64 + ch * 32) * 512
        + mc * 32 + (lane << 2);

    float4 a = {0.f, 0.f, 0.f, 0.f};
#pragma unroll
    for (int j0 = 0; j0 < 32; j0 += 8) {
        float4 v[8];
#pragma unroll
        for (int k = 0; k < 8; k++)
            v[k] = __ldcs(reinterpret_cast<const float4*>(base + (size_t)(j0 + k) * 512));
#pragma unroll
        for (int k = 0; k < 8; k++) {
            a.x += v[k].x; a.y += v[k].y; a.z += v[k].z; a.w += v[k].w;
        }
    }

    __shared__ float4 part[2][32][8];    // [colhalf][row&31][lane], 8 KB
    __shared__ int s_last;
    part[ch][g & 31][lane] = a;
    __syncthreads();

    const int pair = mc * 64 + b;        // counter index
    if (tid < 64) {
        const int c2 = tid >> 5;         // col half
        const int ml = tid & 31;         // m_local
        const float* pf = (const float*)part;
        float ssum = 0.f;
#pragma unroll
        for (int r = 0; r < 32; r++)
            ssum += pf[(c2 * 32 + r) * 32 + ml];
        const int n = b * 512 + mc * 32 + ml;
        g_quads[n * 4 + rh * 2 + c2] = ssum;
    }
    __threadfence();                     // publish g_quads writes
    __syncthreads();
    if (tid == 0) {
        int old = atomicAdd(&g_cnt[pair], 1);
        s_last = (old == 1);
    }
    __syncthreads();

    if (s_last) {
        if (tid < 32) {
            __threadfence();             // acquire partner's g_quads
            const int ml = tid;
            const int n  = b * 512 + mc * 32 + ml;
            float4 qv = *reinterpret_cast<const float4*>(&g_quads[n * 4]);
            float x[4];
            x[0] = tanhf(qv.x * (1.0f / 1024.0f));
            x[1] = tanhf(qv.y * (1.0f / 1024.0f));
            x[2] = tanhf(qv.z * (1.0f / 1024.0f));
            x[3] = tanhf(qv.w * (1.0f / 1024.0f));
            // widx = b*8 + (mm>>6); mm = mc*32+ml, ml<32 => mm>>6 == mc>>1 (uniform)
            const float* wp = w + (size_t)(b * 8 + (mc >> 1)) * 24;
            out[n] = simulate_sample(x, wp);
        }
        if (tid == 0) g_cnt[pair] = 0;   // self-reset for next graph replay
    }
}

extern "C" void kernel_launch(void* const* d_in, const int* in_sizes, int n_in,
                              void* d_out, int out_size)
{
    const float* in = (const float*)d_in[0];
    const float* w  = (const float*)d_in[1];
    if (n_in >= 2 && in_sizes[0] < in_sizes[1]) {   // defensive: identify by size
        in = (const float*)d_in[1];
        w  = (const float*)d_in[0];
    }
    dim3 grid(16, 64, 2);
    qpl_kernel<<<grid, 512>>>(in, w, (float*)d_out);
}